// round 14
// baseline (speedup 1.0000x reference)
#include <cuda_runtime.h>
#include <cuda_fp16.h>
#include <mma.h>

// ---------------------------------------------------------------------------
// ReactionCenterPredictor
//   inputs: 0 atoms[N,32] f32 | 1 bond_energies[E,1] f32 | 2 W_e[1,1] | 3 b_e[1]
//           4 W1[16,33] | 5 b1[16] | 6 W2[1,16] | 7 b2[1] | 8 edge_index[2,E] i64/i32
//   output: [E/2] f32
//
// v8 (resubmit after infra failure): edge register diet
//     (__launch_bounds__(256,5), weights re-read from shared, inline address
//     recompute) to raise occupancy 45% -> ~62% and close the gap to the L1
//     gather floor. Proj unchanged (near DRAM floor).
// ---------------------------------------------------------------------------

#define MAX_N 1000000

__device__ __align__(16) __half g_projh[MAX_N * 16];  // 32 MB fp16 projection table
__device__ int g_idx32;                               // 1 if edge_index is int32

__device__ __forceinline__ __half2 u2h(unsigned u) {
    return *reinterpret_cast<__half2*>(&u);
}

using namespace nvcuda;

// ---------------------------------------------------------------------------
// K1: [n,32] @ [32,16] via wmma tf32 m16n16k8, 8 tiles/warp.
// A staged: coalesced LDG.128 -> regs -> STS (ld=36 pad) -> load_matrix_sync,
// with next tile prefetched into regs during current tile's mma/pack.
// ---------------------------------------------------------------------------
#define PROJ_TPW 8           // tiles per warp
#define PROJ_TPB 64          // tiles per block (8 warps)
#define A_LD 36              // A staging row stride (floats)
#define SC_LD 24             // C staging row stride (floats)

__global__ __launch_bounds__(256) void proj_kernel(
        const float* __restrict__ atoms,
        const float* __restrict__ W1,   // [16,33]
        const float* __restrict__ b1,   // [16]
        const unsigned int* __restrict__ ei_u32,
        int n) {
    __shared__ __align__(16) float sB[32 * 16];          // [j][k] W1 transposed
    __shared__ __align__(16) float sA[8][16 * A_LD];     // per-warp A staging
    __shared__ __align__(16) float sC[8][16 * SC_LD];    // per-warp accum staging
    __shared__ float sb1[16];

    int tid = threadIdx.x;
    int wid = tid >> 5;
    int l = tid & 31;

    if (blockIdx.x == 0 && tid == 0) {
        unsigned int acc = 0;
#pragma unroll
        for (int i = 1; i < 128; i += 2) acc |= __ldg(ei_u32 + i);
        g_idx32 = (acc != 0) ? 1 : 0;
    }

    for (int idx = tid; idx < 32 * 16; idx += 256) {
        int j = idx >> 4, k = idx & 15;
        sB[idx] = __ldg(W1 + k * 33 + j);
    }
    if (tid < 16) sb1[tid] = __ldg(b1 + tid);
    __syncthreads();

    // B fragments (shared across all tiles of this warp).
    wmma::fragment<wmma::matrix_b, 16, 16, 8, wmma::precision::tf32, wmma::row_major> bF[4];
#pragma unroll
    for (int s = 0; s < 4; s++) {
        wmma::load_matrix_sync(bF[s], sB + s * 8 * 16, 16);
#pragma unroll
        for (int t = 0; t < bF[s].num_elements; t++)
            bF[s].x[t] = wmma::__float_to_tf32(bF[s].x[t]);
    }

    // Staging lane constants: float4 idx = i*32 + l -> (row, c4).
    int strow[4], stc4[4];
#pragma unroll
    for (int i = 0; i < 4; i++) {
        int idx = i * 32 + l;
        strow[i] = idx >> 3;
        stc4[i] = idx & 7;
    }

    // Pack lane constants: atom_local = l>>1, half = l&1.
    int atom_local = l >> 1;
    int half = l & 1;
    float hb[8];
#pragma unroll
    for (int i = 0; i < 8; i++) hb[i] = 0.5f * sb1[half * 8 + i];

    int tiles = n >> 4;
    int tile0 = blockIdx.x * PROJ_TPB + wid * PROJ_TPW;
    float* sAw = sA[wid];
    float* sCw = sC[wid];

    int nt = tiles - tile0;
    if (nt > PROJ_TPW) nt = PROJ_TPW;

    float4 buf[4];
    if (nt > 0) {
        const float4* ap = reinterpret_cast<const float4*>(atoms) + (size_t)tile0 * 128;
#pragma unroll
        for (int i = 0; i < 4; i++) buf[i] = __ldg(ap + i * 32 + l);
    }

    for (int t = 0; t < nt; t++) {
        // Stage current tile (coalesced regs -> shared, padded rows).
#pragma unroll
        for (int i = 0; i < 4; i++)
            *reinterpret_cast<float4*>(&sAw[strow[i] * A_LD + stc4[i] * 4]) = buf[i];
        __syncwarp();

        // Prefetch next tile while mma/pack of current proceeds.
        if (t + 1 < nt) {
            const float4* ap =
                reinterpret_cast<const float4*>(atoms) + (size_t)(tile0 + t + 1) * 128;
#pragma unroll
            for (int i = 0; i < 4; i++) buf[i] = __ldg(ap + i * 32 + l);
        }

        wmma::fragment<wmma::accumulator, 16, 16, 8, float> cF;
        wmma::fill_fragment(cF, 0.0f);
#pragma unroll
        for (int s = 0; s < 4; s++) {
            wmma::fragment<wmma::matrix_a, 16, 16, 8, wmma::precision::tf32, wmma::row_major> aF;
            wmma::load_matrix_sync(aF, sAw + s * 8, A_LD);
#pragma unroll
            for (int q = 0; q < aF.num_elements; q++)
                aF.x[q] = wmma::__float_to_tf32(aF.x[q]);
            wmma::mma_sync(cF, aF, bF[s], cF);
        }
        wmma::store_matrix_sync(sCw, cF, SC_LD, wmma::mem_row_major);
        __syncwarp();   // sA fully read (load_matrix done) + sC visible

        // Pack: lane -> one uint4 (8 k's) of one atom row.
        const float4* src = reinterpret_cast<const float4*>(sCw + atom_local * SC_LD + half * 8);
        float4 p0 = src[0], p1 = src[1];
        __half2 h0 = __floats2half2_rn(p0.x + hb[0], p0.y + hb[1]);
        __half2 h1 = __floats2half2_rn(p0.z + hb[2], p0.w + hb[3]);
        __half2 h2 = __floats2half2_rn(p1.x + hb[4], p1.y + hb[5]);
        __half2 h3 = __floats2half2_rn(p1.z + hb[6], p1.w + hb[7]);
        uint4 o;
        o.x = *reinterpret_cast<unsigned*>(&h0);
        o.y = *reinterpret_cast<unsigned*>(&h1);
        o.z = *reinterpret_cast<unsigned*>(&h2);
        o.w = *reinterpret_cast<unsigned*>(&h3);
        int tile = tile0 + t;
        reinterpret_cast<uint4*>(g_projh)[((size_t)tile * 16 + atom_local) * 2 + half] = o;
    }

    // Remainder atoms (n % 16), scalar path in block 0.
    int rem = n & 15;
    if (blockIdx.x == 0 && tid < rem) {
        int atom = tiles * 16 + tid;
        const float* ar = atoms + (size_t)atom * 32;
        unsigned u[8];
#pragma unroll
        for (int c = 0; c < 8; c++) {
            float acc0 = 0.5f * sb1[2 * c], acc1 = 0.5f * sb1[2 * c + 1];
            for (int j = 0; j < 32; j++) {
                float aj = __ldg(ar + j);
                acc0 = fmaf(aj, sB[j * 16 + 2 * c], acc0);
                acc1 = fmaf(aj, sB[j * 16 + 2 * c + 1], acc1);
            }
            __half2 h = __floats2half2_rn(acc0, acc1);
            u[c] = *reinterpret_cast<unsigned*>(&h);
        }
        uint4* dst = reinterpret_cast<uint4*>(g_projh) + (size_t)atom * 2;
        dst[0] = make_uint4(u[0], u[1], u[2], u[3]);
        dst[1] = make_uint4(u[4], u[5], u[6], u[7]);
    }
}

// ---------------------------------------------------------------------------
// K2: 4 lanes per output, each lane loads BOTH endpoint half-rows.
// 32 outputs/warp, 4-deep front-batched gathers. Register diet: weights
// re-read from shared per use, addresses recomputed inline, minblocks=5.
//   dot-combine : shfl_xor 1   (other sub)
//   pair average: shfl_xor 2   (other edge)
// ---------------------------------------------------------------------------
__global__ __launch_bounds__(256, 5) void edge_kernel(
        const float* __restrict__ be,
        const void* __restrict__ ei_raw,
        const float* __restrict__ W1,
        const float* __restrict__ W2,
        const float* __restrict__ We,
        const float* __restrict__ bE,
        const float* __restrict__ b2,
        float* __restrict__ out,
        int E, int H) {
    __shared__ __align__(16) float2 swp[16];  // {W1[k][32], W2[k]}
    __shared__ float sWe, sbe0, sb2;
    __shared__ int sidx32;

    int tid = threadIdx.x;
    if (tid < 16) {
        swp[tid] = make_float2(__ldg(W1 + tid * 33 + 32), __ldg(W2 + tid));
    } else if (tid == 16) sWe = __ldg(We);
    else if (tid == 17) sbe0 = __ldg(bE);
    else if (tid == 18) sb2 = __ldg(b2);
    else if (tid == 19) sidx32 = g_idx32;
    __syncthreads();

    int gtid = blockIdx.x * blockDim.x + tid;
    int w = gtid >> 5;
    int l = gtid & 31;
    int base0 = w * 32;
    if (base0 >= H) return;  // warp-uniform

    int sub = l & 1;
    int eselH = ((l >> 1) & 1) ? H : 0;
    int slot = l >> 2;

    const float4* wp = reinterpret_cast<const float4*>(swp) + sub * 4;
    const unsigned FULL = 0xffffffffu;

    bool full = (base0 + 32 <= H);  // warp-uniform
    int e0 = base0 + slot + eselH;  // e(it) = e0 + 8*it on the fast path

    // Front-batch: index loads, then gathers (4-deep, 8 lines in flight).
    int rs[4], rd[4];
    if (sidx32) {
        const int* p = reinterpret_cast<const int*>(ei_raw);
        if (full) {
#pragma unroll
            for (int it = 0; it < 4; it++) {
                rs[it] = __ldg(p + e0 + 8 * it);
                rd[it] = __ldg(p + e0 + 8 * it + E);
            }
        } else {
#pragma unroll
            for (int it = 0; it < 4; it++) {
                int e = min(base0 + 8 * it + slot, H - 1) + eselH;
                rs[it] = __ldg(p + e);
                rd[it] = __ldg(p + e + E);
            }
        }
    } else {
        const long long* p = reinterpret_cast<const long long*>(ei_raw);
        if (full) {
#pragma unroll
            for (int it = 0; it < 4; it++) {
                rs[it] = (int)__ldg(p + e0 + 8 * it);
                rd[it] = (int)__ldg(p + e0 + 8 * it + E);
            }
        } else {
#pragma unroll
            for (int it = 0; it < 4; it++) {
                int e = min(base0 + 8 * it + slot, H - 1) + eselH;
                rs[it] = (int)__ldg(p + e);
                rd[it] = (int)__ldg(p + e + E);
            }
        }
    }

    const uint4* tab = reinterpret_cast<const uint4*>(g_projh);
    uint4 vs[4], vd[4];
#pragma unroll
    for (int it = 0; it < 4; it++) vs[it] = __ldg(tab + (size_t)rs[it] * 2 + sub);
#pragma unroll
    for (int it = 0; it < 4; it++) vd[it] = __ldg(tab + (size_t)rd[it] * 2 + sub);

#pragma unroll
    for (int it = 0; it < 4; it++) {
        int e = full ? (e0 + 8 * it) : (min(base0 + 8 * it + slot, H - 1) + eselH);

        // Endpoint sum in half2 — no shuffles.
        float2 f0 = __half22float2(__hadd2(u2h(vs[it].x), u2h(vd[it].x)));
        float2 f1 = __half22float2(__hadd2(u2h(vs[it].y), u2h(vd[it].y)));
        float2 f2 = __half22float2(__hadd2(u2h(vs[it].z), u2h(vd[it].z)));
        float2 f3 = __half22float2(__hadd2(u2h(vs[it].w), u2h(vd[it].w)));

        float ef = fmaf(__ldg(be + e), sWe, sbe0);

        float lg;
        {
            float4 wv = wp[0];
            float h0 = fmaxf(fmaf(ef, wv.x, f0.x), 0.0f);
            float h1 = fmaxf(fmaf(ef, wv.z, f0.y), 0.0f);
            lg = h0 * wv.y;
            lg = fmaf(h1, wv.w, lg);
        }
        {
            float4 wv = wp[1];
            float h0 = fmaxf(fmaf(ef, wv.x, f1.x), 0.0f);
            float h1 = fmaxf(fmaf(ef, wv.z, f1.y), 0.0f);
            lg = fmaf(h0, wv.y, lg);
            lg = fmaf(h1, wv.w, lg);
        }
        {
            float4 wv = wp[2];
            float h0 = fmaxf(fmaf(ef, wv.x, f2.x), 0.0f);
            float h1 = fmaxf(fmaf(ef, wv.z, f2.y), 0.0f);
            lg = fmaf(h0, wv.y, lg);
            lg = fmaf(h1, wv.w, lg);
        }
        {
            float4 wv = wp[3];
            float h0 = fmaxf(fmaf(ef, wv.x, f3.x), 0.0f);
            float h1 = fmaxf(fmaf(ef, wv.z, f3.y), 0.0f);
            lg = fmaf(h0, wv.y, lg);
            lg = fmaf(h1, wv.w, lg);
        }

        lg += __shfl_xor_sync(FULL, lg, 1);   // other sub (row half)
        lg += sb2;
        float sc = 1.0f / (1.0f + __expf(-lg));

        float res = 0.5f * (sc + __shfl_xor_sync(FULL, sc, 2));  // other edge of pair

        int oR = base0 + it * 8 + slot;
        if ((l & 3) == 0 && (full || oR < H)) out[oR] = res;
    }
}

// ---------------------------------------------------------------------------

extern "C" void kernel_launch(void* const* d_in, const int* in_sizes, int n_in,
                              void* d_out, int out_size) {
    const float* atoms = (const float*)d_in[0];
    const float* be    = (const float*)d_in[1];
    const float* We    = (const float*)d_in[2];
    const float* bE    = (const float*)d_in[3];
    const float* W1    = (const float*)d_in[4];
    const float* b1    = (const float*)d_in[5];
    const float* W2    = (const float*)d_in[6];
    const float* b2    = (const float*)d_in[7];
    const void*  ei    = d_in[8];
    float* out = (float*)d_out;

    int n = in_sizes[0] / 32;  // atoms
    int E = in_sizes[1];       // edges
    int H = out_size;          // E/2

    int tiles = n >> 4;
    int pblocks = (tiles + PROJ_TPB - 1) / PROJ_TPB;
    if (pblocks < 1) pblocks = 1;
    proj_kernel<<<pblocks, 256>>>(atoms, W1, b1, (const unsigned int*)ei, n);

    long long warps = ((long long)H + 31) / 32;  // 32 outputs per warp
    long long threads = warps * 32;
    int blocks = (int)((threads + 255) / 256);
    edge_kernel<<<blocks, 256>>>(be, ei, W1, W2, We, bE, b2, out, E, H);
}

// round 15
// speedup vs baseline: 1.0920x; 1.0920x over previous
#include <cuda_runtime.h>
#include <cuda_fp16.h>

// ---------------------------------------------------------------------------
// ReactionCenterPredictor
//   inputs: 0 atoms[N,32] f32 | 1 bond_energies[E,1] f32 | 2 W_e[1,1] | 3 b_e[1]
//           4 W1[16,33] | 5 b1[16] | 6 W2[1,16] | 7 b2[1] | 8 edge_index[2,E] i64/i32
//   output: [E/2] f32
//
// v9: edge reverted to v7 (v8's occupancy theory was wrong: LDS weight
//     re-reads added L1tex work) + tanh.approx sigmoid. Proj: documented
//     mma.m16n8k8.tf32 with bias-in-accumulator and direct register->fp16
//     pack (sC shared round-trip deleted).
// ---------------------------------------------------------------------------

#define MAX_N 1000000

__device__ __align__(16) __half g_projh[MAX_N * 16];  // 32 MB fp16 projection table
__device__ int g_idx32;                               // 1 if edge_index is int32

__device__ __forceinline__ __half2 u2h(unsigned u) {
    return *reinterpret_cast<__half2*>(&u);
}
__device__ __forceinline__ unsigned f2tf32(float f) {
    unsigned r;
    asm("cvt.rna.tf32.f32 %0, %1;" : "=r"(r) : "f"(f));
    return r;
}
__device__ __forceinline__ float tanh_approx(float x) {
    float r;
    asm("tanh.approx.f32 %0, %1;" : "=f"(r) : "f"(x));
    return r;
}
__device__ __forceinline__ void mma_16n8k8(float d[4], const unsigned a[4],
                                           const unsigned b[2]) {
    asm("mma.sync.aligned.m16n8k8.row.col.f32.tf32.tf32.f32 "
        "{%0,%1,%2,%3}, {%4,%5,%6,%7}, {%8,%9}, {%0,%1,%2,%3};"
        : "+f"(d[0]), "+f"(d[1]), "+f"(d[2]), "+f"(d[3])
        : "r"(a[0]), "r"(a[1]), "r"(a[2]), "r"(a[3]), "r"(b[0]), "r"(b[1]));
}

// ---------------------------------------------------------------------------
// K1: [n,32] @ [32,16] via mma.m16n8k8.tf32, 8 tiles/warp.
// A staged: coalesced LDG.128 -> regs -> STS (ld=36 pad) -> scalar LDS per
// the documented A-fragment layout; next tile prefetched during compute.
// Bias preloaded into accumulators; D packed to fp16 in-register (no sC).
// ---------------------------------------------------------------------------
#define PROJ_TPW 8           // tiles per warp
#define PROJ_TPB 64          // tiles per block (8 warps)
#define A_LD 36              // A staging row stride (floats)

__global__ __launch_bounds__(256) void proj_kernel(
        const float* __restrict__ atoms,
        const float* __restrict__ W1,   // [16,33]
        const float* __restrict__ b1,   // [16]
        const unsigned int* __restrict__ ei_u32,
        int n) {
    __shared__ __align__(16) float sB[32 * 16];          // [j][k] W1 transposed
    __shared__ __align__(16) float sA[8][16 * A_LD];     // per-warp A staging
    __shared__ float sb1[16];

    int tid = threadIdx.x;
    int wid = tid >> 5;
    int l = tid & 31;

    if (blockIdx.x == 0 && tid == 0) {
        unsigned int acc = 0;
#pragma unroll
        for (int i = 1; i < 128; i += 2) acc |= __ldg(ei_u32 + i);
        g_idx32 = (acc != 0) ? 1 : 0;
    }

    for (int idx = tid; idx < 32 * 16; idx += 256) {
        int j = idx >> 4, k = idx & 15;
        sB[idx] = __ldg(W1 + k * 33 + j);
    }
    if (tid < 16) sb1[tid] = __ldg(b1 + tid);
    __syncthreads();

    int g = l >> 2;        // group id
    int tig = l & 3;       // thread in group

    // B fragments: b[s][nh][2], col-major B of W1t slice s, n-half nh.
    // b0 = B[k=tig][n=g], b1 = B[k=tig+4][n=g]; B[k][n] = sB[(8s+k)*16 + 8nh+n].
    unsigned bf[4][2][2];
#pragma unroll
    for (int s = 0; s < 4; s++)
#pragma unroll
        for (int nh = 0; nh < 2; nh++) {
            bf[s][nh][0] = f2tf32(sB[(8 * s + tig) * 16 + 8 * nh + g]);
            bf[s][nh][1] = f2tf32(sB[(8 * s + tig + 4) * 16 + 8 * nh + g]);
        }

    // Bias for accumulator init: cols (8nh + 2tig, +1).
    float bias0[2], bias1[2];
#pragma unroll
    for (int nh = 0; nh < 2; nh++) {
        bias0[nh] = 0.5f * sb1[8 * nh + 2 * tig];
        bias1[nh] = 0.5f * sb1[8 * nh + 2 * tig + 1];
    }

    // Staging lane constants: float4 idx = i*32 + l -> (row, c4).
    int strow[4], stc4[4];
#pragma unroll
    for (int i = 0; i < 4; i++) {
        int idx = i * 32 + l;
        strow[i] = idx >> 3;
        stc4[i] = idx & 7;
    }

    int tiles = n >> 4;
    int tile0 = blockIdx.x * PROJ_TPB + wid * PROJ_TPW;
    float* sAw = sA[wid];

    int nt = tiles - tile0;
    if (nt > PROJ_TPW) nt = PROJ_TPW;

    float4 buf[4];
    if (nt > 0) {
        const float4* ap = reinterpret_cast<const float4*>(atoms) + (size_t)tile0 * 128;
#pragma unroll
        for (int i = 0; i < 4; i++) buf[i] = __ldg(ap + i * 32 + l);
    }

    unsigned* tabu = reinterpret_cast<unsigned*>(g_projh);

    for (int t = 0; t < nt; t++) {
        // Stage current tile (coalesced regs -> shared, padded rows).
#pragma unroll
        for (int i = 0; i < 4; i++)
            *reinterpret_cast<float4*>(&sAw[strow[i] * A_LD + stc4[i] * 4]) = buf[i];
        __syncwarp();

        // Prefetch next tile while compute proceeds.
        if (t + 1 < nt) {
            const float4* ap =
                reinterpret_cast<const float4*>(atoms) + (size_t)(tile0 + t + 1) * 128;
#pragma unroll
            for (int i = 0; i < 4; i++) buf[i] = __ldg(ap + i * 32 + l);
        }

        float d[2][4];
#pragma unroll
        for (int nh = 0; nh < 2; nh++) {
            d[nh][0] = bias0[nh]; d[nh][1] = bias1[nh];
            d[nh][2] = bias0[nh]; d[nh][3] = bias1[nh];
        }

#pragma unroll
        for (int s = 0; s < 4; s++) {
            // A fragment (documented m16n8k8 tf32 layout):
            // a0:(g, tig) a1:(g+8, tig) a2:(g, tig+4) a3:(g+8, tig+4), cols +8s.
            unsigned af[4];
            af[0] = f2tf32(sAw[g * A_LD + tig + 8 * s]);
            af[1] = f2tf32(sAw[(g + 8) * A_LD + tig + 8 * s]);
            af[2] = f2tf32(sAw[g * A_LD + tig + 4 + 8 * s]);
            af[3] = f2tf32(sAw[(g + 8) * A_LD + tig + 4 + 8 * s]);
            mma_16n8k8(d[0], af, bf[s][0]);
            mma_16n8k8(d[1], af, bf[s][1]);
        }
        __syncwarp();   // all lanes done reading sAw before next STS

        // Pack direct from D: c0,c1 -> row g cols (8nh+2tig,+1); c2,c3 -> row g+8.
        int tile = tile0 + t;
        size_t rbase = (size_t)(tile * 16);
#pragma unroll
        for (int nh = 0; nh < 2; nh++) {
            __half2 hlo = __floats2half2_rn(d[nh][0], d[nh][1]);
            __half2 hhi = __floats2half2_rn(d[nh][2], d[nh][3]);
            tabu[(rbase + g) * 8 + 4 * nh + tig]     = *reinterpret_cast<unsigned*>(&hlo);
            tabu[(rbase + g + 8) * 8 + 4 * nh + tig] = *reinterpret_cast<unsigned*>(&hhi);
        }
    }

    // Remainder atoms (n % 16), scalar path in block 0.
    int rem = n & 15;
    if (blockIdx.x == 0 && tid < rem) {
        int atom = tiles * 16 + tid;
        const float* ar = atoms + (size_t)atom * 32;
        unsigned u[8];
#pragma unroll
        for (int c = 0; c < 8; c++) {
            float acc0 = 0.5f * sb1[2 * c], acc1 = 0.5f * sb1[2 * c + 1];
            for (int j = 0; j < 32; j++) {
                float aj = __ldg(ar + j);
                acc0 = fmaf(aj, sB[j * 16 + 2 * c], acc0);
                acc1 = fmaf(aj, sB[j * 16 + 2 * c + 1], acc1);
            }
            __half2 h = __floats2half2_rn(acc0, acc1);
            u[c] = *reinterpret_cast<unsigned*>(&h);
        }
        uint4* dst = reinterpret_cast<uint4*>(g_projh) + (size_t)atom * 2;
        dst[0] = make_uint4(u[0], u[1], u[2], u[3]);
        dst[1] = make_uint4(u[4], u[5], u[6], u[7]);
    }
}

// ---------------------------------------------------------------------------
// K2 (v7 structure): 4 lanes per output, each lane loads BOTH endpoint
// half-rows (no endpoint shuffles). 32 outputs/warp, loads front-batched.
// Sigmoid via tanh.approx.
//   dot-combine : shfl_xor 1   (other sub)
//   pair average: shfl_xor 2   (other edge)
// ---------------------------------------------------------------------------
struct EdgeW { float4 wv[4]; };  // 8 x {W1_energy, W2} pairs for this sub

__global__ __launch_bounds__(256) void edge_kernel(
        const float* __restrict__ be,
        const void* __restrict__ ei_raw,
        const float* __restrict__ W1,
        const float* __restrict__ W2,
        const float* __restrict__ We,
        const float* __restrict__ bE,
        const float* __restrict__ b2,
        float* __restrict__ out,
        int E, int H) {
    __shared__ __align__(16) float2 swp[16];  // {W1[k][32], W2[k]}
    __shared__ float sWe, sbe0, sb2;
    __shared__ int sidx32;

    int tid = threadIdx.x;
    if (tid < 16) {
        swp[tid] = make_float2(__ldg(W1 + tid * 33 + 32), __ldg(W2 + tid));
    } else if (tid == 16) sWe = __ldg(We);
    else if (tid == 17) sbe0 = __ldg(bE);
    else if (tid == 18) sb2 = __ldg(b2);
    else if (tid == 19) sidx32 = g_idx32;
    __syncthreads();

    int gtid = blockIdx.x * blockDim.x + tid;
    int w = gtid >> 5;
    int l = gtid & 31;
    int base0 = w * 32;
    if (base0 >= H) return;  // warp-uniform

    int sub = l & 1;
    int eselH = ((l >> 1) & 1) ? H : 0;
    int slot = l >> 2;

    EdgeW W;
    {
        const float4* wp = reinterpret_cast<const float4*>(swp) + sub * 4;
#pragma unroll
        for (int t = 0; t < 4; t++) W.wv[t] = wp[t];
    }
    float Wev = sWe, be0v = sbe0, b2v = sb2;
    int idx32 = sidx32;
    const unsigned FULL = 0xffffffffu;

    bool full = (base0 + 32 <= H);  // warp-uniform fast path
    int eA[4];
    if (full) {
#pragma unroll
        for (int it = 0; it < 4; it++) eA[it] = base0 + it * 8 + slot + eselH;
    } else {
#pragma unroll
        for (int it = 0; it < 4; it++) eA[it] = min(base0 + it * 8 + slot, H - 1) + eselH;
    }

    // Front-batch: all index loads, then all gathers, then all energies.
    int rs[4], rd[4];
    if (idx32) {
        const int* p = reinterpret_cast<const int*>(ei_raw);
#pragma unroll
        for (int it = 0; it < 4; it++) { rs[it] = __ldg(p + eA[it]); rd[it] = __ldg(p + eA[it] + E); }
    } else {
        const long long* p = reinterpret_cast<const long long*>(ei_raw);
#pragma unroll
        for (int it = 0; it < 4; it++) { rs[it] = (int)__ldg(p + eA[it]); rd[it] = (int)__ldg(p + eA[it] + E); }
    }

    const uint4* tab = reinterpret_cast<const uint4*>(g_projh);
    uint4 vs[4], vd[4];
#pragma unroll
    for (int it = 0; it < 4; it++) vs[it] = __ldg(tab + (size_t)rs[it] * 2 + sub);
#pragma unroll
    for (int it = 0; it < 4; it++) vd[it] = __ldg(tab + (size_t)rd[it] * 2 + sub);

    float bev[4];
#pragma unroll
    for (int it = 0; it < 4; it++) bev[it] = __ldg(be + eA[it]);

#pragma unroll
    for (int it = 0; it < 4; it++) {
        // Endpoint sum in half2 — no shuffles.
        float2 f0 = __half22float2(__hadd2(u2h(vs[it].x), u2h(vd[it].x)));
        float2 f1 = __half22float2(__hadd2(u2h(vs[it].y), u2h(vd[it].y)));
        float2 f2 = __half22float2(__hadd2(u2h(vs[it].z), u2h(vd[it].z)));
        float2 f3 = __half22float2(__hadd2(u2h(vs[it].w), u2h(vd[it].w)));

        float ef = fmaf(bev[it], Wev, be0v);

        float lg;
        {
            float4 wv = W.wv[0];
            float h0 = fmaxf(fmaf(ef, wv.x, f0.x), 0.0f);
            float h1 = fmaxf(fmaf(ef, wv.z, f0.y), 0.0f);
            lg = h0 * wv.y;
            lg = fmaf(h1, wv.w, lg);
        }
        {
            float4 wv = W.wv[1];
            float h0 = fmaxf(fmaf(ef, wv.x, f1.x), 0.0f);
            float h1 = fmaxf(fmaf(ef, wv.z, f1.y), 0.0f);
            lg = fmaf(h0, wv.y, lg);
            lg = fmaf(h1, wv.w, lg);
        }
        {
            float4 wv = W.wv[2];
            float h0 = fmaxf(fmaf(ef, wv.x, f2.x), 0.0f);
            float h1 = fmaxf(fmaf(ef, wv.z, f2.y), 0.0f);
            lg = fmaf(h0, wv.y, lg);
            lg = fmaf(h1, wv.w, lg);
        }
        {
            float4 wv = W.wv[3];
            float h0 = fmaxf(fmaf(ef, wv.x, f3.x), 0.0f);
            float h1 = fmaxf(fmaf(ef, wv.z, f3.y), 0.0f);
            lg = fmaf(h0, wv.y, lg);
            lg = fmaf(h1, wv.w, lg);
        }

        lg += __shfl_xor_sync(FULL, lg, 1);   // other sub (row half)
        lg += b2v;
        // sigmoid(x) = 0.5*tanh(x/2) + 0.5
        float sc = fmaf(tanh_approx(0.5f * lg), 0.5f, 0.5f);

        float res = 0.5f * (sc + __shfl_xor_sync(FULL, sc, 2));  // other edge of pair

        int oR = base0 + it * 8 + slot;
        if ((l & 3) == 0 && (full || oR < H)) out[oR] = res;
    }
}

// ---------------------------------------------------------------------------

extern "C" void kernel_launch(void* const* d_in, const int* in_sizes, int n_in,
                              void* d_out, int out_size) {
    const float* atoms = (const float*)d_in[0];
    const float* be    = (const float*)d_in[1];
    const float* We    = (const float*)d_in[2];
    const float* bE    = (const float*)d_in[3];
    const float* W1    = (const float*)d_in[4];
    const float* b1    = (const float*)d_in[5];
    const float* W2    = (const float*)d_in[6];
    const float* b2    = (const float*)d_in[7];
    const void*  ei    = d_in[8];
    float* out = (float*)d_out;

    int n = in_sizes[0] / 32;  // atoms
    int E = in_sizes[1];       // edges
    int H = out_size;          // E/2

    int tiles = n >> 4;
    int pblocks = (tiles + PROJ_TPB - 1) / PROJ_TPB;
    if (pblocks < 1) pblocks = 1;
    proj_kernel<<<pblocks, 256>>>(atoms, W1, b1, (const unsigned int*)ei, n);

    long long warps = ((long long)H + 31) / 32;  // 32 outputs per warp
    long long threads = warps * 32;
    int blocks = (int)((threads + 255) / 256);
    edge_kernel<<<blocks, 256>>>(be, ei, W1, W2, We, bE, b2, out, E, H);
}

// round 16
// speedup vs baseline: 1.1152x; 1.0213x over previous
#include <cuda_runtime.h>
#include <cuda_fp16.h>

// ---------------------------------------------------------------------------
// ReactionCenterPredictor
//   inputs: 0 atoms[N,32] f32 | 1 bond_energies[E,1] f32 | 2 W_e[1,1] | 3 b_e[1]
//           4 W1[16,33] | 5 b1[16] | 6 W2[1,16] | 7 b2[1] | 8 edge_index[2,E] i64/i32
//   output: [E/2] f32
//
// v10: permuted projection-row word order so proj writes are 2x STG.64 per
//      lane (100% sector efficiency; was 4x strided STG.32 at 50%). Edge's
//      weight table is permuted to match — its data path is unchanged.
//      Row word p holds column pair (8*(p&1) + 2*(p>>1), +1).
// ---------------------------------------------------------------------------

#define MAX_N 1000000

__device__ __align__(16) __half g_projh[MAX_N * 16];  // 32 MB fp16 projection table
__device__ int g_idx32;                               // 1 if edge_index is int32

__device__ __forceinline__ __half2 u2h(unsigned u) {
    return *reinterpret_cast<__half2*>(&u);
}
__device__ __forceinline__ unsigned f2tf32(float f) {
    unsigned r;
    asm("cvt.rna.tf32.f32 %0, %1;" : "=r"(r) : "f"(f));
    return r;
}
__device__ __forceinline__ float tanh_approx(float x) {
    float r;
    asm("tanh.approx.f32 %0, %1;" : "=f"(r) : "f"(x));
    return r;
}
__device__ __forceinline__ unsigned h2pack(float a, float b) {
    __half2 h = __floats2half2_rn(a, b);
    return *reinterpret_cast<unsigned*>(&h);
}
__device__ __forceinline__ void mma_16n8k8(float d[4], const unsigned a[4],
                                           const unsigned b[2]) {
    asm("mma.sync.aligned.m16n8k8.row.col.f32.tf32.tf32.f32 "
        "{%0,%1,%2,%3}, {%4,%5,%6,%7}, {%8,%9}, {%0,%1,%2,%3};"
        : "+f"(d[0]), "+f"(d[1]), "+f"(d[2]), "+f"(d[3])
        : "r"(a[0]), "r"(a[1]), "r"(a[2]), "r"(a[3]), "r"(b[0]), "r"(b[1]));
}

// ---------------------------------------------------------------------------
// K1: [n,32] @ [32,16] via mma.m16n8k8.tf32, 8 tiles/warp.
// A staged: coalesced LDG.128 -> regs -> STS (ld=36 pad) -> scalar LDS per
// the documented A-fragment layout; next tile prefetched during compute.
// Bias preloaded into accumulators; D packed to fp16 in-register.
// Store: lane (g,tig) writes rows g and g+8 at word offset 2*tig as uint2
// (permuted layout: word 2*tig+nh = this lane's nh column pair).
// ---------------------------------------------------------------------------
#define PROJ_TPW 8           // tiles per warp
#define PROJ_TPB 64          // tiles per block (8 warps)
#define A_LD 36              // A staging row stride (floats)

__global__ __launch_bounds__(256) void proj_kernel(
        const float* __restrict__ atoms,
        const float* __restrict__ W1,   // [16,33]
        const float* __restrict__ b1,   // [16]
        const unsigned int* __restrict__ ei_u32,
        int n) {
    __shared__ __align__(16) float sB[32 * 16];          // [j][k] W1 transposed
    __shared__ __align__(16) float sA[8][16 * A_LD];     // per-warp A staging
    __shared__ float sb1[16];

    int tid = threadIdx.x;
    int wid = tid >> 5;
    int l = tid & 31;

    if (blockIdx.x == 0 && tid == 0) {
        unsigned int acc = 0;
#pragma unroll
        for (int i = 1; i < 128; i += 2) acc |= __ldg(ei_u32 + i);
        g_idx32 = (acc != 0) ? 1 : 0;
    }

    for (int idx = tid; idx < 32 * 16; idx += 256) {
        int j = idx >> 4, k = idx & 15;
        sB[idx] = __ldg(W1 + k * 33 + j);
    }
    if (tid < 16) sb1[tid] = __ldg(b1 + tid);
    __syncthreads();

    int g = l >> 2;        // group id
    int tig = l & 3;       // thread in group

    // B fragments: b[s][nh][2], col-major B of W1t slice s, n-half nh.
    unsigned bf[4][2][2];
#pragma unroll
    for (int s = 0; s < 4; s++)
#pragma unroll
        for (int nh = 0; nh < 2; nh++) {
            bf[s][nh][0] = f2tf32(sB[(8 * s + tig) * 16 + 8 * nh + g]);
            bf[s][nh][1] = f2tf32(sB[(8 * s + tig + 4) * 16 + 8 * nh + g]);
        }

    // Bias for accumulator init: cols (8nh + 2tig, +1).
    float bias0[2], bias1[2];
#pragma unroll
    for (int nh = 0; nh < 2; nh++) {
        bias0[nh] = 0.5f * sb1[8 * nh + 2 * tig];
        bias1[nh] = 0.5f * sb1[8 * nh + 2 * tig + 1];
    }

    // Staging lane constants: float4 idx = i*32 + l -> (row, c4).
    int strow[4], stc4[4];
#pragma unroll
    for (int i = 0; i < 4; i++) {
        int idx = i * 32 + l;
        strow[i] = idx >> 3;
        stc4[i] = idx & 7;
    }

    int tiles = n >> 4;
    int tile0 = blockIdx.x * PROJ_TPB + wid * PROJ_TPW;
    float* sAw = sA[wid];

    int nt = tiles - tile0;
    if (nt > PROJ_TPW) nt = PROJ_TPW;

    float4 buf[4];
    if (nt > 0) {
        const float4* ap = reinterpret_cast<const float4*>(atoms) + (size_t)tile0 * 128;
#pragma unroll
        for (int i = 0; i < 4; i++) buf[i] = __ldg(ap + i * 32 + l);
    }

    uint2* tab2 = reinterpret_cast<uint2*>(g_projh);

    for (int t = 0; t < nt; t++) {
        // Stage current tile (coalesced regs -> shared, padded rows).
#pragma unroll
        for (int i = 0; i < 4; i++)
            *reinterpret_cast<float4*>(&sAw[strow[i] * A_LD + stc4[i] * 4]) = buf[i];
        __syncwarp();

        // Prefetch next tile while compute proceeds.
        if (t + 1 < nt) {
            const float4* ap =
                reinterpret_cast<const float4*>(atoms) + (size_t)(tile0 + t + 1) * 128;
#pragma unroll
            for (int i = 0; i < 4; i++) buf[i] = __ldg(ap + i * 32 + l);
        }

        float d[2][4];
#pragma unroll
        for (int nh = 0; nh < 2; nh++) {
            d[nh][0] = bias0[nh]; d[nh][1] = bias1[nh];
            d[nh][2] = bias0[nh]; d[nh][3] = bias1[nh];
        }

#pragma unroll
        for (int s = 0; s < 4; s++) {
            unsigned af[4];
            af[0] = f2tf32(sAw[g * A_LD + tig + 8 * s]);
            af[1] = f2tf32(sAw[(g + 8) * A_LD + tig + 8 * s]);
            af[2] = f2tf32(sAw[g * A_LD + tig + 4 + 8 * s]);
            af[3] = f2tf32(sAw[(g + 8) * A_LD + tig + 4 + 8 * s]);
            mma_16n8k8(d[0], af, bf[s][0]);
            mma_16n8k8(d[1], af, bf[s][1]);
        }
        __syncwarp();   // all lanes done reading sAw before next STS

        // Permuted pack: lane writes rows g / g+8, words (2tig, 2tig+1).
        int tile = tile0 + t;
        size_t rbase = (size_t)(tile * 16);
        uint2 lo, hi;
        lo.x = h2pack(d[0][0], d[0][1]);   // word 2tig   (nh=0 pair, row g)
        lo.y = h2pack(d[1][0], d[1][1]);   // word 2tig+1 (nh=1 pair, row g)
        hi.x = h2pack(d[0][2], d[0][3]);   // row g+8
        hi.y = h2pack(d[1][2], d[1][3]);
        tab2[(rbase + g) * 4 + tig] = lo;
        tab2[(rbase + g + 8) * 4 + tig] = hi;
    }

    // Remainder atoms (n % 16), scalar path in block 0 (permuted word order:
    // word p holds cols (8*(p&1)+2*(p>>1), +1) -> old pair index 4*(p&1)+(p>>1)).
    int rem = n & 15;
    if (blockIdx.x == 0 && tid < rem) {
        int atom = tiles * 16 + tid;
        const float* ar = atoms + (size_t)atom * 32;
        unsigned u[8];
#pragma unroll
        for (int c = 0; c < 8; c++) {
            float acc0 = 0.5f * sb1[2 * c], acc1 = 0.5f * sb1[2 * c + 1];
            for (int j = 0; j < 32; j++) {
                float aj = __ldg(ar + j);
                acc0 = fmaf(aj, sB[j * 16 + 2 * c], acc0);
                acc1 = fmaf(aj, sB[j * 16 + 2 * c + 1], acc1);
            }
            u[c] = h2pack(acc0, acc1);
        }
        uint4* dst = reinterpret_cast<uint4*>(g_projh) + (size_t)atom * 2;
        dst[0] = make_uint4(u[0], u[4], u[1], u[5]);
        dst[1] = make_uint4(u[2], u[6], u[3], u[7]);
    }
}

// ---------------------------------------------------------------------------
// K2 (v9 structure, permuted weight table): 4 lanes per output, each lane
// loads BOTH endpoint half-rows. 32 outputs/warp, loads front-batched.
// Sigmoid via tanh.approx.
//   swp entry e: p = e>>1, h = e&1 -> k = 8*(p&1) + 2*(p>>1) + h, matching
//   table word p's column pair.
// ---------------------------------------------------------------------------
struct EdgeW { float4 wv[4]; };  // 8 x {W1_energy, W2} pairs for this sub

__global__ __launch_bounds__(256) void edge_kernel(
        const float* __restrict__ be,
        const void* __restrict__ ei_raw,
        const float* __restrict__ W1,
        const float* __restrict__ W2,
        const float* __restrict__ We,
        const float* __restrict__ bE,
        const float* __restrict__ b2,
        float* __restrict__ out,
        int E, int H) {
    __shared__ __align__(16) float2 swp[16];  // permuted {W1[k][32], W2[k]}
    __shared__ float sWe, sbe0, sb2;
    __shared__ int sidx32;

    int tid = threadIdx.x;
    if (tid < 16) {
        int p = tid >> 1, h = tid & 1;
        int k = ((p & 1) << 3) + ((p >> 1) << 1) + h;
        swp[tid] = make_float2(__ldg(W1 + k * 33 + 32), __ldg(W2 + k));
    } else if (tid == 16) sWe = __ldg(We);
    else if (tid == 17) sbe0 = __ldg(bE);
    else if (tid == 18) sb2 = __ldg(b2);
    else if (tid == 19) sidx32 = g_idx32;
    __syncthreads();

    int gtid = blockIdx.x * blockDim.x + tid;
    int w = gtid >> 5;
    int l = gtid & 31;
    int base0 = w * 32;
    if (base0 >= H) return;  // warp-uniform

    int sub = l & 1;
    int eselH = ((l >> 1) & 1) ? H : 0;
    int slot = l >> 2;

    EdgeW W;
    {
        const float4* wp = reinterpret_cast<const float4*>(swp) + sub * 4;
#pragma unroll
        for (int t = 0; t < 4; t++) W.wv[t] = wp[t];
    }
    float Wev = sWe, be0v = sbe0, b2v = sb2;
    int idx32 = sidx32;
    const unsigned FULL = 0xffffffffu;

    bool full = (base0 + 32 <= H);  // warp-uniform fast path
    int eA[4];
    if (full) {
#pragma unroll
        for (int it = 0; it < 4; it++) eA[it] = base0 + it * 8 + slot + eselH;
    } else {
#pragma unroll
        for (int it = 0; it < 4; it++) eA[it] = min(base0 + it * 8 + slot, H - 1) + eselH;
    }

    // Front-batch: all index loads, then all gathers, then all energies.
    int rs[4], rd[4];
    if (idx32) {
        const int* p = reinterpret_cast<const int*>(ei_raw);
#pragma unroll
        for (int it = 0; it < 4; it++) { rs[it] = __ldg(p + eA[it]); rd[it] = __ldg(p + eA[it] + E); }
    } else {
        const long long* p = reinterpret_cast<const long long*>(ei_raw);
#pragma unroll
        for (int it = 0; it < 4; it++) { rs[it] = (int)__ldg(p + eA[it]); rd[it] = (int)__ldg(p + eA[it] + E); }
    }

    const uint4* tab = reinterpret_cast<const uint4*>(g_projh);
    uint4 vs[4], vd[4];
#pragma unroll
    for (int it = 0; it < 4; it++) vs[it] = __ldg(tab + (size_t)rs[it] * 2 + sub);
#pragma unroll
    for (int it = 0; it < 4; it++) vd[it] = __ldg(tab + (size_t)rd[it] * 2 + sub);

    float bev[4];
#pragma unroll
    for (int it = 0; it < 4; it++) bev[it] = __ldg(be + eA[it]);

#pragma unroll
    for (int it = 0; it < 4; it++) {
        // Endpoint sum in half2 — no shuffles.
        float2 f0 = __half22float2(__hadd2(u2h(vs[it].x), u2h(vd[it].x)));
        float2 f1 = __half22float2(__hadd2(u2h(vs[it].y), u2h(vd[it].y)));
        float2 f2 = __half22float2(__hadd2(u2h(vs[it].z), u2h(vd[it].z)));
        float2 f3 = __half22float2(__hadd2(u2h(vs[it].w), u2h(vd[it].w)));

        float ef = fmaf(bev[it], Wev, be0v);

        float lg;
        {
            float4 wv = W.wv[0];
            float h0 = fmaxf(fmaf(ef, wv.x, f0.x), 0.0f);
            float h1 = fmaxf(fmaf(ef, wv.z, f0.y), 0.0f);
            lg = h0 * wv.y;
            lg = fmaf(h1, wv.w, lg);
        }
        {
            float4 wv = W.wv[1];
            float h0 = fmaxf(fmaf(ef, wv.x, f1.x), 0.0f);
            float h1 = fmaxf(fmaf(ef, wv.z, f1.y), 0.0f);
            lg = fmaf(h0, wv.y, lg);
            lg = fmaf(h1, wv.w, lg);
        }
        {
            float4 wv = W.wv[2];
            float h0 = fmaxf(fmaf(ef, wv.x, f2.x), 0.0f);
            float h1 = fmaxf(fmaf(ef, wv.z, f2.y), 0.0f);
            lg = fmaf(h0, wv.y, lg);
            lg = fmaf(h1, wv.w, lg);
        }
        {
            float4 wv = W.wv[3];
            float h0 = fmaxf(fmaf(ef, wv.x, f3.x), 0.0f);
            float h1 = fmaxf(fmaf(ef, wv.z, f3.y), 0.0f);
            lg = fmaf(h0, wv.y, lg);
            lg = fmaf(h1, wv.w, lg);
        }

        lg += __shfl_xor_sync(FULL, lg, 1);   // other sub (row half)
        lg += b2v;
        // sigmoid(x) = 0.5*tanh(x/2) + 0.5
        float sc = fmaf(tanh_approx(0.5f * lg), 0.5f, 0.5f);

        float res = 0.5f * (sc + __shfl_xor_sync(FULL, sc, 2));  // other edge of pair

        int oR = base0 + it * 8 + slot;
        if ((l & 3) == 0 && (full || oR < H)) out[oR] = res;
    }
}

// ---------------------------------------------------------------------------

extern "C" void kernel_launch(void* const* d_in, const int* in_sizes, int n_in,
                              void* d_out, int out_size) {
    const float* atoms = (const float*)d_in[0];
    const float* be    = (const float*)d_in[1];
    const float* We    = (const float*)d_in[2];
    const float* bE    = (const float*)d_in[3];
    const float* W1    = (const float*)d_in[4];
    const float* b1    = (const float*)d_in[5];
    const float* W2    = (const float*)d_in[6];
    const float* b2    = (const float*)d_in[7];
    const void*  ei    = d_in[8];
    float* out = (float*)d_out;

    int n = in_sizes[0] / 32;  // atoms
    int E = in_sizes[1];       // edges
    int H = out_size;          // E/2

    int tiles = n >> 4;
    int pblocks = (tiles + PROJ_TPB - 1) / PROJ_TPB;
    if (pblocks < 1) pblocks = 1;
    proj_kernel<<<pblocks, 256>>>(atoms, W1, b1, (const unsigned int*)ei, n);

    long long warps = ((long long)H + 31) / 32;  // 32 outputs per warp
    long long threads = warps * 32;
    int blocks = (int)((threads + 255) / 256);
    edge_kernel<<<blocks, 256>>>(be, ei, W1, W2, We, bE, b2, out, E, H);
}

// round 17
// speedup vs baseline: 1.2372x; 1.1094x over previous
#include <cuda_runtime.h>
#include <cuda_fp16.h>

// ---------------------------------------------------------------------------
// ReactionCenterPredictor
//   inputs: 0 atoms[N,32] f32 | 1 bond_energies[E,1] f32 | 2 W_e[1,1] | 3 b_e[1]
//           4 W1[16,33] | 5 b1[16] | 6 W2[1,16] | 7 b2[1] | 8 edge_index[2,E] i64/i32
//   output: [E/2] f32
//
// v11: persistent rolling-refill edge kernel — each warp loops over batches,
//      refilling each gather register the instant it is consumed (prefetch
//      distance 2 for indices), keeping ~16 loads permanently in flight per
//      warp. Proj identical to v10 (permuted-word table, mma tf32).
// ---------------------------------------------------------------------------

#define MAX_N 1000000

__device__ __align__(16) __half g_projh[MAX_N * 16];  // 32 MB fp16 projection table
__device__ int g_idx32;                               // 1 if edge_index is int32

__device__ __forceinline__ __half2 u2h(unsigned u) {
    return *reinterpret_cast<__half2*>(&u);
}
__device__ __forceinline__ unsigned f2tf32(float f) {
    unsigned r;
    asm("cvt.rna.tf32.f32 %0, %1;" : "=r"(r) : "f"(f));
    return r;
}
__device__ __forceinline__ float tanh_approx(float x) {
    float r;
    asm("tanh.approx.f32 %0, %1;" : "=f"(r) : "f"(x));
    return r;
}
__device__ __forceinline__ unsigned h2pack(float a, float b) {
    __half2 h = __floats2half2_rn(a, b);
    return *reinterpret_cast<unsigned*>(&h);
}
__device__ __forceinline__ void mma_16n8k8(float d[4], const unsigned a[4],
                                           const unsigned b[2]) {
    asm("mma.sync.aligned.m16n8k8.row.col.f32.tf32.tf32.f32 "
        "{%0,%1,%2,%3}, {%4,%5,%6,%7}, {%8,%9}, {%0,%1,%2,%3};"
        : "+f"(d[0]), "+f"(d[1]), "+f"(d[2]), "+f"(d[3])
        : "r"(a[0]), "r"(a[1]), "r"(a[2]), "r"(a[3]), "r"(b[0]), "r"(b[1]));
}

// ---------------------------------------------------------------------------
// K1 (v10): [n,32] @ [32,16] via mma.m16n8k8.tf32, 8 tiles/warp, permuted
// output word order (word p = columns 8*(p&1)+2*(p>>1), +1), 2x STG.64/lane.
// ---------------------------------------------------------------------------
#define PROJ_TPW 8           // tiles per warp
#define PROJ_TPB 64          // tiles per block (8 warps)
#define A_LD 36              // A staging row stride (floats)

__global__ __launch_bounds__(256) void proj_kernel(
        const float* __restrict__ atoms,
        const float* __restrict__ W1,   // [16,33]
        const float* __restrict__ b1,   // [16]
        const unsigned int* __restrict__ ei_u32,
        int n) {
    __shared__ __align__(16) float sB[32 * 16];          // [j][k] W1 transposed
    __shared__ __align__(16) float sA[8][16 * A_LD];     // per-warp A staging
    __shared__ float sb1[16];

    int tid = threadIdx.x;
    int wid = tid >> 5;
    int l = tid & 31;

    if (blockIdx.x == 0 && tid == 0) {
        unsigned int acc = 0;
#pragma unroll
        for (int i = 1; i < 128; i += 2) acc |= __ldg(ei_u32 + i);
        g_idx32 = (acc != 0) ? 1 : 0;
    }

    for (int idx = tid; idx < 32 * 16; idx += 256) {
        int j = idx >> 4, k = idx & 15;
        sB[idx] = __ldg(W1 + k * 33 + j);
    }
    if (tid < 16) sb1[tid] = __ldg(b1 + tid);
    __syncthreads();

    int g = l >> 2;        // group id
    int tig = l & 3;       // thread in group

    unsigned bf[4][2][2];
#pragma unroll
    for (int s = 0; s < 4; s++)
#pragma unroll
        for (int nh = 0; nh < 2; nh++) {
            bf[s][nh][0] = f2tf32(sB[(8 * s + tig) * 16 + 8 * nh + g]);
            bf[s][nh][1] = f2tf32(sB[(8 * s + tig + 4) * 16 + 8 * nh + g]);
        }

    float bias0[2], bias1[2];
#pragma unroll
    for (int nh = 0; nh < 2; nh++) {
        bias0[nh] = 0.5f * sb1[8 * nh + 2 * tig];
        bias1[nh] = 0.5f * sb1[8 * nh + 2 * tig + 1];
    }

    int strow[4], stc4[4];
#pragma unroll
    for (int i = 0; i < 4; i++) {
        int idx = i * 32 + l;
        strow[i] = idx >> 3;
        stc4[i] = idx & 7;
    }

    int tiles = n >> 4;
    int tile0 = blockIdx.x * PROJ_TPB + wid * PROJ_TPW;
    float* sAw = sA[wid];

    int nt = tiles - tile0;
    if (nt > PROJ_TPW) nt = PROJ_TPW;

    float4 buf[4];
    if (nt > 0) {
        const float4* ap = reinterpret_cast<const float4*>(atoms) + (size_t)tile0 * 128;
#pragma unroll
        for (int i = 0; i < 4; i++) buf[i] = __ldg(ap + i * 32 + l);
    }

    uint2* tab2 = reinterpret_cast<uint2*>(g_projh);

    for (int t = 0; t < nt; t++) {
#pragma unroll
        for (int i = 0; i < 4; i++)
            *reinterpret_cast<float4*>(&sAw[strow[i] * A_LD + stc4[i] * 4]) = buf[i];
        __syncwarp();

        if (t + 1 < nt) {
            const float4* ap =
                reinterpret_cast<const float4*>(atoms) + (size_t)(tile0 + t + 1) * 128;
#pragma unroll
            for (int i = 0; i < 4; i++) buf[i] = __ldg(ap + i * 32 + l);
        }

        float d[2][4];
#pragma unroll
        for (int nh = 0; nh < 2; nh++) {
            d[nh][0] = bias0[nh]; d[nh][1] = bias1[nh];
            d[nh][2] = bias0[nh]; d[nh][3] = bias1[nh];
        }

#pragma unroll
        for (int s = 0; s < 4; s++) {
            unsigned af[4];
            af[0] = f2tf32(sAw[g * A_LD + tig + 8 * s]);
            af[1] = f2tf32(sAw[(g + 8) * A_LD + tig + 8 * s]);
            af[2] = f2tf32(sAw[g * A_LD + tig + 4 + 8 * s]);
            af[3] = f2tf32(sAw[(g + 8) * A_LD + tig + 4 + 8 * s]);
            mma_16n8k8(d[0], af, bf[s][0]);
            mma_16n8k8(d[1], af, bf[s][1]);
        }
        __syncwarp();

        int tile = tile0 + t;
        size_t rbase = (size_t)(tile * 16);
        uint2 lo, hi;
        lo.x = h2pack(d[0][0], d[0][1]);
        lo.y = h2pack(d[1][0], d[1][1]);
        hi.x = h2pack(d[0][2], d[0][3]);
        hi.y = h2pack(d[1][2], d[1][3]);
        tab2[(rbase + g) * 4 + tig] = lo;
        tab2[(rbase + g + 8) * 4 + tig] = hi;
    }

    int rem = n & 15;
    if (blockIdx.x == 0 && tid < rem) {
        int atom = tiles * 16 + tid;
        const float* ar = atoms + (size_t)atom * 32;
        unsigned u[8];
#pragma unroll
        for (int c = 0; c < 8; c++) {
            float acc0 = 0.5f * sb1[2 * c], acc1 = 0.5f * sb1[2 * c + 1];
            for (int j = 0; j < 32; j++) {
                float aj = __ldg(ar + j);
                acc0 = fmaf(aj, sB[j * 16 + 2 * c], acc0);
                acc1 = fmaf(aj, sB[j * 16 + 2 * c + 1], acc1);
            }
            u[c] = h2pack(acc0, acc1);
        }
        uint4* dst = reinterpret_cast<uint4*>(g_projh) + (size_t)atom * 2;
        dst[0] = make_uint4(u[0], u[4], u[1], u[5]);
        dst[1] = make_uint4(u[2], u[6], u[3], u[7]);
    }
}

// ---------------------------------------------------------------------------
// K2: persistent rolling-refill edge kernel. 4 lanes/output, lane loads both
// endpoint half-rows; batch = 32 outputs/warp. After consuming vs[it]/vd[it]
// the same regs are refilled with the NEXT batch's gather; rsn holds indices
// two batches ahead. Permuted weight table matches the v10 row layout.
// ---------------------------------------------------------------------------
struct EdgeW { float4 wv[4]; };  // 8 x {W1_energy, W2} pairs for this sub

template <typename IT>
__device__ __forceinline__ void edge_loop(
        const IT* __restrict__ ip, const float* __restrict__ be,
        const uint4* __restrict__ tab, float* __restrict__ out,
        int E, int H, int warpG, int nWarp, int nB, int K,
        int sub, int eselH, int slot, const EdgeW& W,
        float Wev, float be0v, float b2v, int l) {
    const unsigned FULL = 0xffffffffu;

    int b0 = warpG;
    int b1 = (b0 + nWarp < nB) ? (b0 + nWarp) : b0;

    int rsn[4], rdn[4];
    uint4 vs[4], vd[4];
    float bev[4];

    // Prologue: idx(b0) -> gathers(b0), be(b0); then idx(b1) into rolling regs.
#pragma unroll
    for (int it = 0; it < 4; it++) {
        int e = min(b0 * 32 + it * 8 + slot, H - 1) + eselH;
        rsn[it] = (int)__ldg(ip + e);
        rdn[it] = (int)__ldg(ip + e + E);
        bev[it] = __ldg(be + e);
    }
#pragma unroll
    for (int it = 0; it < 4; it++) {
        vs[it] = __ldg(tab + (size_t)(unsigned)rsn[it] * 2 + sub);
        vd[it] = __ldg(tab + (size_t)(unsigned)rdn[it] * 2 + sub);
    }
#pragma unroll
    for (int it = 0; it < 4; it++) {
        int e = min(b1 * 32 + it * 8 + slot, H - 1) + eselH;
        rsn[it] = (int)__ldg(ip + e);
        rdn[it] = (int)__ldg(ip + e + E);
    }

    int bCur = b0;
    for (int k = 0; k < K; k++) {
        int bNxt = bCur + nWarp;  if (bNxt >= nB) bNxt = bCur;    // clamped (dead data)
        int bNxt2 = bNxt + nWarp; if (bNxt2 >= nB) bNxt2 = bNxt;
        int oBase = bCur * 32 + slot;

#pragma unroll
        for (int it = 0; it < 4; it++) {
            // --- compute batch bCur, slot it ---
            float2 f0 = __half22float2(__hadd2(u2h(vs[it].x), u2h(vd[it].x)));
            float2 f1 = __half22float2(__hadd2(u2h(vs[it].y), u2h(vd[it].y)));
            float2 f2 = __half22float2(__hadd2(u2h(vs[it].z), u2h(vd[it].z)));
            float2 f3 = __half22float2(__hadd2(u2h(vs[it].w), u2h(vd[it].w)));

            float ef = fmaf(bev[it], Wev, be0v);

            float lg;
            {
                float4 wv = W.wv[0];
                float h0 = fmaxf(fmaf(ef, wv.x, f0.x), 0.0f);
                float h1 = fmaxf(fmaf(ef, wv.z, f0.y), 0.0f);
                lg = h0 * wv.y;
                lg = fmaf(h1, wv.w, lg);
            }
            {
                float4 wv = W.wv[1];
                float h0 = fmaxf(fmaf(ef, wv.x, f1.x), 0.0f);
                float h1 = fmaxf(fmaf(ef, wv.z, f1.y), 0.0f);
                lg = fmaf(h0, wv.y, lg);
                lg = fmaf(h1, wv.w, lg);
            }
            {
                float4 wv = W.wv[2];
                float h0 = fmaxf(fmaf(ef, wv.x, f2.x), 0.0f);
                float h1 = fmaxf(fmaf(ef, wv.z, f2.y), 0.0f);
                lg = fmaf(h0, wv.y, lg);
                lg = fmaf(h1, wv.w, lg);
            }
            {
                float4 wv = W.wv[3];
                float h0 = fmaxf(fmaf(ef, wv.x, f3.x), 0.0f);
                float h1 = fmaxf(fmaf(ef, wv.z, f3.y), 0.0f);
                lg = fmaf(h0, wv.y, lg);
                lg = fmaf(h1, wv.w, lg);
            }

            lg += __shfl_xor_sync(FULL, lg, 1);   // other sub (row half)
            lg += b2v;
            float sc = fmaf(tanh_approx(0.5f * lg), 0.5f, 0.5f);
            float res = 0.5f * (sc + __shfl_xor_sync(FULL, sc, 2));

            int oR = oBase + it * 8;
            if ((l & 3) == 0 && oR < H) out[oR] = res;

            // --- refill slot it: gather(bNxt) from rolling idx, idx(bNxt2) ---
            vs[it] = __ldg(tab + (size_t)(unsigned)rsn[it] * 2 + sub);
            vd[it] = __ldg(tab + (size_t)(unsigned)rdn[it] * 2 + sub);
            int eN = min(bNxt * 32 + it * 8 + slot, H - 1) + eselH;
            bev[it] = __ldg(be + eN);
            int eN2 = min(bNxt2 * 32 + it * 8 + slot, H - 1) + eselH;
            rsn[it] = (int)__ldg(ip + eN2);
            rdn[it] = (int)__ldg(ip + eN2 + E);
        }
        bCur = bNxt;
    }
}

__global__ __launch_bounds__(256) void edge_kernel(
        const float* __restrict__ be,
        const void* __restrict__ ei_raw,
        const float* __restrict__ W1,
        const float* __restrict__ W2,
        const float* __restrict__ We,
        const float* __restrict__ bE,
        const float* __restrict__ b2,
        float* __restrict__ out,
        int E, int H) {
    __shared__ __align__(16) float2 swp[16];  // permuted {W1[k][32], W2[k]}
    __shared__ float sWe, sbe0, sb2;
    __shared__ int sidx32;

    int tid = threadIdx.x;
    if (tid < 16) {
        int p = tid >> 1, h = tid & 1;
        int k = ((p & 1) << 3) + ((p >> 1) << 1) + h;
        swp[tid] = make_float2(__ldg(W1 + k * 33 + 32), __ldg(W2 + k));
    } else if (tid == 16) sWe = __ldg(We);
    else if (tid == 17) sbe0 = __ldg(bE);
    else if (tid == 18) sb2 = __ldg(b2);
    else if (tid == 19) sidx32 = g_idx32;
    __syncthreads();

    int l = tid & 31;
    int warpG = (blockIdx.x * blockDim.x + tid) >> 5;
    int nWarp = (gridDim.x * blockDim.x) >> 5;
    int nB = (H + 31) >> 5;
    if (warpG >= nB) return;
    int K = (nB - warpG + nWarp - 1) / nWarp;

    int sub = l & 1;
    int eselH = ((l >> 1) & 1) ? H : 0;
    int slot = l >> 2;

    EdgeW W;
    {
        const float4* wp = reinterpret_cast<const float4*>(swp) + sub * 4;
#pragma unroll
        for (int t = 0; t < 4; t++) W.wv[t] = wp[t];
    }

    const uint4* tab = reinterpret_cast<const uint4*>(g_projh);
    if (sidx32) {
        edge_loop<int>(reinterpret_cast<const int*>(ei_raw), be, tab, out,
                       E, H, warpG, nWarp, nB, K, sub, eselH, slot, W,
                       sWe, sbe0, sb2, l);
    } else {
        edge_loop<long long>(reinterpret_cast<const long long*>(ei_raw), be, tab, out,
                             E, H, warpG, nWarp, nB, K, sub, eselH, slot, W,
                             sWe, sbe0, sb2, l);
    }
}

// ---------------------------------------------------------------------------

extern "C" void kernel_launch(void* const* d_in, const int* in_sizes, int n_in,
                              void* d_out, int out_size) {
    const float* atoms = (const float*)d_in[0];
    const float* be    = (const float*)d_in[1];
    const float* We    = (const float*)d_in[2];
    const float* bE    = (const float*)d_in[3];
    const float* W1    = (const float*)d_in[4];
    const float* b1    = (const float*)d_in[5];
    const float* W2    = (const float*)d_in[6];
    const float* b2    = (const float*)d_in[7];
    const void*  ei    = d_in[8];
    float* out = (float*)d_out;

    int n = in_sizes[0] / 32;  // atoms
    int E = in_sizes[1];       // edges
    int H = out_size;          // E/2

    int tiles = n >> 4;
    int pblocks = (tiles + PROJ_TPB - 1) / PROJ_TPB;
    if (pblocks < 1) pblocks = 1;
    proj_kernel<<<pblocks, 256>>>(atoms, W1, b1, (const unsigned int*)ei, n);

    // Persistent edge grid: 592 CTAs (grid-stride by warp), work-conserving
    // for any residency.
    int nB = (H + 31) >> 5;
    int eblocks = 592;
    if (eblocks * 8 > nB) eblocks = (nB + 7) / 8;  // tiny-H safety
    if (eblocks < 1) eblocks = 1;
    edge_kernel<<<eblocks, 256>>>(be, ei, W1, W2, We, bE, b2, out, E, H);
}